// round 2
// baseline (speedup 1.0000x reference)
#include <cuda_runtime.h>
#include <math.h>

// Problem constants
#define NB    32
#define NH    12
#define GRID  14          // GH == GW
#define LTOK  196         // GRID*GRID
#define DHEAD 64
#define NSTEP 13          // steps 1..13
#define CHUNK 32          // d-chunk per block (DHEAD/2)
#define TPB   224         // threads per block; tasks = 14*32 = 448 = 2*TPB

// out[b,h,m,d] = x[b,h,m,d]
//   + sum_{dir,step valid} C[h][dir][step][d] * x[b,h,neighbor(m,dir,step),d]
// C[h][dir][step][d] = sd(step)*P[dir*4+si][d][h] + nd(step)*P[dir*4+si+1][d][h],
// P = param_1 + param_2. Separable: 13 vertical + 13 horizontal taps.

__global__ __launch_bounds__(TPB, 6)
void save_kernel(const float* __restrict__ x,
                 const float* __restrict__ p1,
                 const float* __restrict__ p2,
                 float* __restrict__ out)
{
    __shared__ float xs[LTOK * CHUNK];           // 25088 B
    __shared__ float Cs[4 * NSTEP * CHUNK];      //  6656 B
    __shared__ float sd_s[NSTEP], nd_s[NSTEP];
    __shared__ int   si_s[NSTEP];

    const int blk = blockIdx.x;       // (b*NH + h) * 2 + dhalf
    const int bh  = blk >> 1;
    const int dlo = (blk & 1) * CHUNK;
    const int hd  = bh % NH;
    const int tid = threadIdx.x;

    const float* xb = x   + (size_t)bh * (LTOK * DHEAD);
    float*       ob = out + (size_t)bh * (LTOK * DHEAD);

    // step weights (double precision, matches reference table build)
    if (tid < NSTEP) {
        int step = tid + 1;
        double interp = 3.0 * (double)(step - 1) / 13.0;
        int si = (int)interp;
        double dist = exp(-(double)(step * step) / 196.0);
        sd_s[tid] = (float)(dist * (1.0 - (interp - (double)si)));
        nd_s[tid] = (float)(dist * (interp - (double)si));
        si_s[tid] = si;
    }

    // load x tile (d-half) into smem, float4-vectorized: 8 float4 per row
    {
        const float4* x4  = (const float4*)(xb + dlo);
        float4*       xs4 = (float4*)xs;
        #pragma unroll
        for (int it = 0; it < (LTOK * 8) / TPB; it++) {
            int i   = tid + it * TPB;
            int row = i >> 3;
            int c4  = i & 7;
            xs4[i] = x4[row * (DHEAD / 4) + c4];
        }
    }
    __syncthreads();

    // build per-(head, d-half) coefficients: Cs[dir][step][d_local]
    // param layout: param[(k*DHEAD + d)*NH + h]
    for (int i = tid; i < 4 * NSTEP * CHUNK; i += TPB) {
        int d    = i & (CHUNK - 1);
        int sidx = (i >> 5) % NSTEP;
        int dir  = i / (NSTEP * CHUNK);
        int si   = si_s[sidx];
        int k0   = dir * 4 + si;
        int ia   = (k0 * DHEAD + dlo + d) * NH + hd;
        int ib   = ((k0 + 1) * DHEAD + dlo + d) * NH + hd;
        float pa = p1[ia] + p2[ia];
        float pb = p1[ib] + p2[ib];
        Cs[i] = sd_s[sidx] * pa + nd_s[sidx] * pb;
    }
    __syncthreads();

    // ===== V phase: out = x + vertical conv (2 static tasks per thread) =====
    #pragma unroll 1
    for (int t = 0; t < 2; t++) {
        int v = tid + t * TPB;          // 0..447
        int d = v & (CHUNK - 1);
        int w = v >> 5;                 // 0..13

        float xc[GRID];
        #pragma unroll
        for (int hh = 0; hh < GRID; hh++)
            xc[hh] = xs[(hh * GRID + w) * CHUNK + d];

        float acc[GRID];
        {   // direction 0: top (h - s)
            float c[NSTEP];
            #pragma unroll
            for (int s = 0; s < NSTEP; s++) c[s] = Cs[(0 * NSTEP + s) * CHUNK + d];
            #pragma unroll
            for (int hh = 0; hh < GRID; hh++) {
                float a = xc[hh];
                #pragma unroll
                for (int s = 1; s <= hh; s++) a = fmaf(c[s - 1], xc[hh - s], a);
                acc[hh] = a;
            }
        }
        {   // direction 1: bottom (h + s)
            float c[NSTEP];
            #pragma unroll
            for (int s = 0; s < NSTEP; s++) c[s] = Cs[(1 * NSTEP + s) * CHUNK + d];
            #pragma unroll
            for (int hh = 0; hh < GRID; hh++) {
                float a = acc[hh];
                #pragma unroll
                for (int s = 1; s <= NSTEP - hh; s++) a = fmaf(c[s - 1], xc[hh + s], a);
                acc[hh] = a;
            }
        }
        #pragma unroll
        for (int hh = 0; hh < GRID; hh++)
            ob[(hh * GRID + w) * DHEAD + dlo + d] = acc[hh];
    }
    __syncthreads();   // V-phase global stores visible before H-phase RMW (same block)

    // ===== H phase: out += horizontal conv =====
    #pragma unroll 1
    for (int t = 0; t < 2; t++) {
        int v  = tid + t * TPB;
        int d  = v & (CHUNK - 1);
        int hr = v >> 5;

        float xr[GRID];
        #pragma unroll
        for (int ww = 0; ww < GRID; ww++)
            xr[ww] = xs[(hr * GRID + ww) * CHUNK + d];

        float acc[GRID];
        {   // direction 2: left (w - s)
            float c[NSTEP];
            #pragma unroll
            for (int s = 0; s < NSTEP; s++) c[s] = Cs[(2 * NSTEP + s) * CHUNK + d];
            #pragma unroll
            for (int ww = 0; ww < GRID; ww++) {
                float a = 0.0f;
                #pragma unroll
                for (int s = 1; s <= ww; s++) a = fmaf(c[s - 1], xr[ww - s], a);
                acc[ww] = a;
            }
        }
        {   // direction 3: right (w + s)
            float c[NSTEP];
            #pragma unroll
            for (int s = 0; s < NSTEP; s++) c[s] = Cs[(3 * NSTEP + s) * CHUNK + d];
            #pragma unroll
            for (int ww = 0; ww < GRID; ww++) {
                float a = acc[ww];
                #pragma unroll
                for (int s = 1; s <= NSTEP - ww; s++) a = fmaf(c[s - 1], xr[ww + s], a);
                acc[ww] = a;
            }
        }
        #pragma unroll
        for (int ww = 0; ww < GRID; ww++) {
            int idx = (hr * GRID + ww) * DHEAD + dlo + d;
            ob[idx] += acc[ww];   // exclusive per element; V result ordered by syncthreads
        }
    }
}

extern "C" void kernel_launch(void* const* d_in, const int* in_sizes, int n_in,
                              void* d_out, int out_size)
{
    // metadata order: x, table, param_1, param_2 (table recomputed analytically)
    const float* x  = (const float*)d_in[0];
    const float* p1 = (const float*)d_in[2];
    const float* p2 = (const float*)d_in[3];
    float*       out = (float*)d_out;

    save_kernel<<<NB * NH * 2, TPB>>>(x, p1, p2, out);
}

// round 5
// speedup vs baseline: 1.5319x; 1.5319x over previous
#include <cuda_runtime.h>
#include <math.h>

// Problem constants
#define NB    32
#define NH    12
#define GRID  14          // GH == GW
#define LTOK  196         // GRID*GRID
#define DHEAD 64
#define NSTEP 13          // steps 1..13
#define CHUNK 32          // d-chunk per block (DHEAD/2)
#define TPB   224         // 7 warps; tasks = 14*32 = 448 = 2*TPB

// out[b,h,m,d] = x[b,h,m,d]
//   + sum_{dir,step valid} C[h][dir][step][d] * x[b,h,neighbor(m,dir,step),d]
// C[h][dir][step][d] = sd(step)*P[dir*4+si][d][h] + nd(step)*P[dir*4+si+1][d][h],
// P = param_1 + param_2.  Separable: ys = x + V(x) in smem, out = ys + H(x).

__global__ __launch_bounds__(TPB, 4)
void save_kernel(const float* __restrict__ x,
                 const float* __restrict__ p1,
                 const float* __restrict__ p2,
                 float* __restrict__ out)
{
    __shared__ float xs[LTOK * CHUNK];           // 25088 B : x tile (d-half)
    __shared__ float ys[LTOK * CHUNK];           // 25088 B : x + V(x)
    __shared__ float Cs[4 * NSTEP * CHUNK];      //  6656 B : per-(head,d) coeffs
    __shared__ float sd_s[NSTEP], nd_s[NSTEP];
    __shared__ int   si_s[NSTEP];

    const int blk = blockIdx.x;       // (b*NH + h) * 2 + dhalf
    const int bh  = blk >> 1;
    const int dlo = (blk & 1) * CHUNK;
    const int hd  = bh % NH;
    const int tid = threadIdx.x;

    const float* xb = x   + (size_t)bh * (LTOK * DHEAD);
    float*       ob = out + (size_t)bh * (LTOK * DHEAD);

    // step weights (double precision, matches reference table build)
    if (tid < NSTEP) {
        int step = tid + 1;
        double interp = 3.0 * (double)(step - 1) / 13.0;
        int si = (int)interp;
        double dist = exp(-(double)(step * step) / 196.0);
        sd_s[tid] = (float)(dist * (1.0 - (interp - (double)si)));
        nd_s[tid] = (float)(dist * (interp - (double)si));
        si_s[tid] = si;
    }

    // load x tile (d-half) into smem, float4-vectorized: 8 float4 per token
    {
        const float4* x4  = (const float4*)(xb + dlo);
        float4*       xs4 = (float4*)xs;
        #pragma unroll
        for (int it = 0; it < (LTOK * (CHUNK / 4)) / TPB; it++) {
            int i   = tid + it * TPB;
            int row = i >> 3;
            int c4  = i & 7;
            xs4[i] = x4[row * (DHEAD / 4) + c4];
        }
    }

    // build coefficients Cs[dir][step][d_local]; param layout: p[(k*DHEAD+d)*NH + h]
    __syncthreads();   // sd_s/si_s ready
    for (int i = tid; i < 4 * NSTEP * CHUNK; i += TPB) {
        int d    = i & (CHUNK - 1);
        int sidx = (i >> 5) % NSTEP;
        int dir  = i / (NSTEP * CHUNK);
        int si   = si_s[sidx];
        int k0   = dir * 4 + si;
        int ia   = (k0 * DHEAD + dlo + d) * NH + hd;
        int ib   = ((k0 + 1) * DHEAD + dlo + d) * NH + hd;
        float pa = p1[ia] + p2[ia];
        float pb = p1[ib] + p2[ib];
        Cs[i] = sd_s[sidx] * pa + nd_s[sidx] * pb;
    }
    __syncthreads();

    const int d  = tid & (CHUNK - 1);
    const int g0 = tid >> 5;            // 0..6 ; task t uses g0 + 7*t

    // ===== V phase: ys = x + vertical conv =====
    {
        float c0[NSTEP], c1[NSTEP];      // shared across both tasks (same d)
        #pragma unroll
        for (int s = 0; s < NSTEP; s++) {
            c0[s] = Cs[(0 * NSTEP + s) * CHUNK + d];   // top    (h - s)
            c1[s] = Cs[(1 * NSTEP + s) * CHUNK + d];   // bottom (h + s)
        }
        #pragma unroll 1
        for (int t = 0; t < 2; t++) {
            int w = g0 + 7 * t;

            float xc[GRID];
            #pragma unroll
            for (int hh = 0; hh < GRID; hh++)
                xc[hh] = xs[(hh * GRID + w) * CHUNK + d];

            #pragma unroll
            for (int hh = 0; hh < GRID; hh++) {
                float a = xc[hh];
                #pragma unroll
                for (int s = 1; s <= hh; s++)
                    a = fmaf(c0[s - 1], xc[hh - s], a);
                #pragma unroll
                for (int s = 1; s <= NSTEP - hh; s++)
                    a = fmaf(c1[s - 1], xc[hh + s], a);
                ys[(hh * GRID + w) * CHUNK + d] = a;
            }
        }
    }
    __syncthreads();   // ys complete before reads

    // ===== H phase: out = ys + horizontal conv (single gmem write) =====
    {
        float c2[NSTEP], c3[NSTEP];
        #pragma unroll
        for (int s = 0; s < NSTEP; s++) {
            c2[s] = Cs[(2 * NSTEP + s) * CHUNK + d];   // left  (w - s)
            c3[s] = Cs[(3 * NSTEP + s) * CHUNK + d];   // right (w + s)
        }
        #pragma unroll 1
        for (int t = 0; t < 2; t++) {
            int hr = g0 + 7 * t;

            float xr[GRID];
            #pragma unroll
            for (int ww = 0; ww < GRID; ww++)
                xr[ww] = xs[(hr * GRID + ww) * CHUNK + d];

            #pragma unroll
            for (int ww = 0; ww < GRID; ww++) {
                float a = 0.0f;
                #pragma unroll
                for (int s = 1; s <= ww; s++)
                    a = fmaf(c2[s - 1], xr[ww - s], a);
                #pragma unroll
                for (int s = 1; s <= NSTEP - ww; s++)
                    a = fmaf(c3[s - 1], xr[ww + s], a);
                int tok = hr * GRID + ww;
                ob[tok * DHEAD + dlo + d] = ys[tok * CHUNK + d] + a;
            }
        }
    }
}

extern "C" void kernel_launch(void* const* d_in, const int* in_sizes, int n_in,
                              void* d_out, int out_size)
{
    // metadata order: x, table, param_1, param_2 (table recomputed analytically)
    const float* x  = (const float*)d_in[0];
    const float* p1 = (const float*)d_in[2];
    const float* p2 = (const float*)d_in[3];
    float*       out = (float*)d_out;

    save_kernel<<<NB * NH * 2, TPB>>>(x, p1, p2, out);
}

// round 6
// speedup vs baseline: 1.6814x; 1.0976x over previous
#include <cuda_runtime.h>

// Problem constants
#define NB    32
#define NH    12
#define GRID  14          // GH == GW
#define LTOK  196         // GRID*GRID
#define DHEAD 64
#define NSTEP 13          // steps 1..13
#define CHUNK 32          // d-chunk per block (DHEAD/2)
#define TPB   224         // 7 warps; tasks = 14*32 = 448 = 2*TPB

// out[b,h,m,d] = x[b,h,m,d]
//   + sum_{dir,step valid} C[h][dir][step][d] * x[b,h,neighbor(m,dir,step),d]
// C[h][dir][step][d] = sd(step)*P[dir*4+si][d][h] + nd(step)*P[dir*4+si+1][d][h],
// P = param_1 + param_2.  Separable: ys = x + V(x) in smem, out = ys + H(x).
//
// Step tables (precomputed, matches reference double-precision build to ~1e-7):
//   interp = 3*(step-1)/13 ; si = floor(interp) ; frac = interp - si
//   dist   = exp(-step^2/196)
__constant__ float DIST_C[NSTEP] = {
    0.9949110f, 0.9797987f, 0.9551199f, 0.9216104f, 0.8802485f,
    0.8322075f, 0.7788008f, 0.7214223f, 0.6614868f, 0.6003730f,
    0.5393734f, 0.4796523f, 0.4222132f };
__constant__ float FRAC_C[NSTEP] = {
    0.00000000f, 0.23076923f, 0.46153846f, 0.69230769f, 0.92307692f,
    0.15384615f, 0.38461538f, 0.61538462f, 0.84615385f, 0.07692308f,
    0.30769231f, 0.53846154f, 0.76923077f };
__constant__ int SI_C[NSTEP] = { 0,0,0,0,0, 1,1,1,1, 2,2,2,2 };

__global__ __launch_bounds__(TPB, 4)
void save_kernel(const float* __restrict__ x,
                 const float* __restrict__ p1,
                 const float* __restrict__ p2,
                 float* __restrict__ out)
{
    __shared__ float xs[LTOK * CHUNK];           // 25088 B : x tile (d-half)
    __shared__ float ys[LTOK * CHUNK];           // 25088 B : x + V(x)
    __shared__ float Cs[4 * NSTEP * CHUNK];      //  6656 B : per-(head,d) coeffs

    const int blk = blockIdx.x;       // (b*NH + h) * 2 + dhalf
    const int bh  = blk >> 1;
    const int dlo = (blk & 1) * CHUNK;
    const int hd  = bh % NH;
    const int tid = threadIdx.x;

    const float* xb = x   + (size_t)bh * (LTOK * DHEAD);
    float*       ob = out + (size_t)bh * (LTOK * DHEAD);

    // ---- load x tile (d-half) into smem, float4-vectorized ----
    {
        const float4* x4  = (const float4*)(xb + dlo);
        float4*       xs4 = (float4*)xs;
        #pragma unroll
        for (int it = 0; it < (LTOK * (CHUNK / 4)) / TPB; it++) {
            int i   = tid + it * TPB;
            int row = i >> 3;
            int c4  = i & 7;
            xs4[i] = x4[row * (DHEAD / 4) + c4];
        }
    }

    // ---- build coefficients Cs[dir][step][d_local] ----
    // param layout: p[(k*DHEAD + d)*NH + h]
    #pragma unroll
    for (int it = 0; it < 8; it++) {
        int i = tid + it * TPB;
        if (i < 4 * NSTEP * CHUNK) {
            int d    = i & (CHUNK - 1);
            int sidx = (i >> 5) % NSTEP;
            int dir  = i / (NSTEP * CHUNK);
            int si   = SI_C[sidx];
            float fr = FRAC_C[sidx];
            float ds = DIST_C[sidx];
            int k0   = dir * 4 + si;
            int ia   = (k0 * DHEAD + dlo + d) * NH + hd;
            int ib   = ((k0 + 1) * DHEAD + dlo + d) * NH + hd;
            float pa = p1[ia] + p2[ia];
            float pb = p1[ib] + p2[ib];
            Cs[i] = ds * (1.0f - fr) * pa + ds * fr * pb;
        }
    }
    __syncthreads();

    const int d  = tid & (CHUNK - 1);
    const int g0 = tid >> 5;            // 0..6 ; task t handles line g0 + 7*t

    // ===== V phase: ys = x + vertical conv (s-outer, interleaved acc) =====
    {
        float c0[NSTEP], c1[NSTEP];      // shared across both tasks (same d)
        #pragma unroll
        for (int s = 0; s < NSTEP; s++) {
            c0[s] = Cs[(0 * NSTEP + s) * CHUNK + d];   // top    (h - s)
            c1[s] = Cs[(1 * NSTEP + s) * CHUNK + d];   // bottom (h + s)
        }
        #pragma unroll 1
        for (int t = 0; t < 2; t++) {
            int w = g0 + 7 * t;

            float xc[GRID], acc[GRID];
            #pragma unroll
            for (int hh = 0; hh < GRID; hh++) {
                xc[hh]  = xs[(hh * GRID + w) * CHUNK + d];
                acc[hh] = xc[hh];
            }
            #pragma unroll
            for (int s = 1; s <= NSTEP; s++) {
                #pragma unroll
                for (int hh = s; hh < GRID; hh++)
                    acc[hh] = fmaf(c0[s - 1], xc[hh - s], acc[hh]);
                #pragma unroll
                for (int hh = 0; hh + s < GRID; hh++)
                    acc[hh] = fmaf(c1[s - 1], xc[hh + s], acc[hh]);
            }
            #pragma unroll
            for (int hh = 0; hh < GRID; hh++)
                ys[(hh * GRID + w) * CHUNK + d] = acc[hh];
        }
    }
    __syncthreads();   // ys complete before H-phase reads

    // ===== H phase: out = ys + horizontal conv (single gmem write) =====
    {
        float c2[NSTEP], c3[NSTEP];
        #pragma unroll
        for (int s = 0; s < NSTEP; s++) {
            c2[s] = Cs[(2 * NSTEP + s) * CHUNK + d];   // left  (w - s)
            c3[s] = Cs[(3 * NSTEP + s) * CHUNK + d];   // right (w + s)
        }
        #pragma unroll 1
        for (int t = 0; t < 2; t++) {
            int hr = g0 + 7 * t;

            float xr[GRID], acc[GRID];
            #pragma unroll
            for (int ww = 0; ww < GRID; ww++) {
                xr[ww]  = xs[(hr * GRID + ww) * CHUNK + d];
                acc[ww] = ys[(hr * GRID + ww) * CHUNK + d];   // x + V already in
            }
            #pragma unroll
            for (int s = 1; s <= NSTEP; s++) {
                #pragma unroll
                for (int ww = s; ww < GRID; ww++)
                    acc[ww] = fmaf(c2[s - 1], xr[ww - s], acc[ww]);
                #pragma unroll
                for (int ww = 0; ww + s < GRID; ww++)
                    acc[ww] = fmaf(c3[s - 1], xr[ww + s], acc[ww]);
            }
            #pragma unroll
            for (int ww = 0; ww < GRID; ww++)
                ob[(hr * GRID + ww) * DHEAD + dlo + d] = acc[ww];
        }
    }
}

extern "C" void kernel_launch(void* const* d_in, const int* in_sizes, int n_in,
                              void* d_out, int out_size)
{
    // metadata order: x, table, param_1, param_2 (table recomputed analytically)
    const float* x  = (const float*)d_in[0];
    const float* p1 = (const float*)d_in[2];
    const float* p2 = (const float*)d_in[3];
    float*       out = (float*)d_out;

    save_kernel<<<NB * NH * 2, TPB>>>(x, p1, p2, out);
}